// round 10
// baseline (speedup 1.0000x reference)
#include <cuda_runtime.h>
#include <cuda_bf16.h>
#include <cstdint>

#define XSTR 528          // row stride bytes (264 bf16): 132 words ≡ 4 mod 32 → conflict-free LDS.64
#define MAXH 128
#define MAXG 16

// device-global bf16 scratch (allowed: static __device__ arrays)
__device__ __align__(16) __nv_bfloat16 g_Eh[100000 * 128];   // E_hist, k-interleaved, 25.6 MB
__device__ __align__(16) __nv_bfloat16 g_Er[1000 * 128];     // E_reg,  k-interleaved
__device__ __align__(16) __nv_bfloat16 g_Wb[256 * 264];      // W1,     k-interleaved + pad

// within each 16-elem chunk, order [0,1,8,9, 2,3,10,11, 4,5,12,13, 6,7,14,15]:
// LDS.64 at byte chunk*32 + tg*8 returns (2tg,2tg+1 | 2tg+8,2tg+9) = one mma fragment pair.
__device__ __forceinline__ int kmap16(int j) {
    return ((j & 7) >> 1) * 4 + ((j >> 3) << 1) + (j & 1);
}

__global__ void convert_kernel(const float* __restrict__ Eh, const float* __restrict__ Er,
                               const float* __restrict__ W1, int nEh, int nEr) {
    long i = (long)blockIdx.x * blockDim.x + threadIdx.x;
    if (i < nEh) {
        int row = (int)(i >> 7), k = (int)(i & 127);
        g_Eh[(long)row * 128 + (k & ~15) + kmap16(k & 15)] = __float2bfloat16(Eh[i]);
    } else if (i < nEh + nEr) {
        long j = i - nEh;
        int row = (int)(j >> 7), k = (int)(j & 127);
        g_Er[(long)row * 128 + (k & ~15) + kmap16(k & 15)] = __float2bfloat16(Er[j]);
    } else if (i < nEh + nEr + 65536) {
        int j = (int)(i - nEh - nEr);
        int n = j >> 8, k = j & 255;
        g_Wb[n * 264 + (k & ~15) + kmap16(k & 15)] = __float2bfloat16(W1[j]);
    }
}

// smem layout (bytes)
static constexpr int SM_W  = 0;                    // 256 x 528 = 135168
static constexpr int SM_X  = 135168;               // 112 x 528 = 59136
static constexpr int SM_IH = 194304;               // MAXG*MAXH ints = 8192
static constexpr int SM_IR = 202496;               // 8192
static constexpr int SM_TV = 210688;               // 544 (512B tvec bf16 + pad)
static constexpr int SM_FL = 211232;               // floats
static constexpr int SMEM_BYTES = SM_FL + 1176 * 4;   // 215936

__device__ __forceinline__ uint32_t smem_u32(const void* p) {
    return (uint32_t)__cvta_generic_to_shared(p);
}
__device__ __forceinline__ void cpa16(uint32_t dst, const void* src) {
    asm volatile("cp.async.ca.shared.global [%0], [%1], 16;" :: "r"(dst), "l"(src));
}
#define CPA_COMMIT() asm volatile("cp.async.commit_group;" ::: "memory")
#define CPA_WAIT0()  asm volatile("cp.async.wait_group 0;" ::: "memory")

__device__ __forceinline__ uint32_t bmul2(uint32_t a, uint32_t t) {
    __nv_bfloat162 x = *reinterpret_cast<__nv_bfloat162*>(&a);
    __nv_bfloat162 y = *reinterpret_cast<__nv_bfloat162*>(&t);
    __nv_bfloat162 r = __hmul2(x, y);
    return *reinterpret_cast<uint32_t*>(&r);
}
__device__ __forceinline__ void mma_bf16(float c[4], uint32_t a0, uint32_t a1, uint32_t a2,
                                         uint32_t a3, uint32_t b0, uint32_t b1) {
    asm volatile(
        "mma.sync.aligned.m16n8k16.row.col.f32.bf16.bf16.f32 "
        "{%0,%1,%2,%3}, {%4,%5,%6,%7}, {%8,%9}, {%0,%1,%2,%3};\n"
        : "+f"(c[0]), "+f"(c[1]), "+f"(c[2]), "+f"(c[3])
        : "r"(a0), "r"(a1), "r"(a2), "r"(a3), "r"(b0), "r"(b1));
}
__device__ __forceinline__ float dot8(uint4 xv, uint4 tv) {
    float s = 0.f;
    const uint32_t* xw = (const uint32_t*)&xv;
    const uint32_t* tw = (const uint32_t*)&tv;
    #pragma unroll
    for (int i = 0; i < 4; ++i) {
        float2 xf = __bfloat1622float2(*reinterpret_cast<const __nv_bfloat162*>(&xw[i]));
        float2 tf = __bfloat1622float2(*reinterpret_cast<const __nv_bfloat162*>(&tw[i]));
        s += xf.x * tf.x + xf.y * tf.y;
    }
    return s;
}

__global__ __launch_bounds__(512, 1)
void nais_kernel(const int* __restrict__ history,
                 const int* __restrict__ target,
                 const int* __restrict__ hregion,
                 const int* __restrict__ tregion,
                 const float* __restrict__ tdist,
                 const float* __restrict__ E_tgt,
                 const float* __restrict__ E_dist,
                 const float* __restrict__ b1,
                 const float* __restrict__ w2,
                 float* __restrict__ out,
                 int B, int H, int G)
{
    extern __shared__ unsigned char smem[];
    unsigned char* Ws = smem + SM_W;               // [256][528] bf16 W (k-interleaved)
    unsigned char* Xs = smem + SM_X;               // [112][528] bf16 raw embeddings
    int* idxH = (int*)(smem + SM_IH);              // [MAXG][MAXH]
    int* idxR = (int*)(smem + SM_IR);
    unsigned char* Tv = smem + SM_TV;              // 512B tvec bf16 (k-interleaved)
    float* fl    = (float*)(smem + SM_FL);
    float* b1s   = fl;            // 256
    float* w2s   = fl + 256;      // 256
    float* sx    = fl + 512;      // 128
    float* spp   = fl + 640;      // 4 x 128
    float* redS  = fl + 1152;     // 16
    float* miscF = fl + 1168;     // 1

    const int tid  = threadIdx.x;
    const int wid  = tid >> 5;
    const int lane = tid & 31;

    const int bbase = blockIdx.x * G;
    if (bbase >= B) return;
    const int gcnt = min(G, B - bbase);

    const uint32_t xs32 = smem_u32(Xs);

    // issue one row of next-batch X via cp.async (1 x 16B per lane)
    auto issue_row = [&](int h, int item, int rg) {
        uint32_t dst = xs32 + h * XSTR;
        if (lane < 16)
            cpa16(dst + lane * 16, (const char*)g_Eh + (size_t)item * 256 + lane * 16);
        else
            cpa16(dst + 256 + (lane - 16) * 16, (const char*)g_Er + (size_t)rg * 256 + (lane - 16) * 16);
    };
    // build tvec for batch nb (called by tid<128)
    auto build_tvec = [&](int nb) {
        int tI = target[nb], tR = tregion[nb];
        float v = E_tgt[(size_t)tI * 128 + tid];
        int pos = (tid & ~15) + kmap16(tid & 15);
        ((__nv_bfloat16*)Tv)[pos] = __float2bfloat16(v);
        if (tid < 64)
            ((uint32_t*)(Tv + 256))[tid] = ((const uint32_t*)((const char*)g_Er + (size_t)tR * 256))[tid];
    };

    // ---------------- prologue ----------------
    {
        const uint4* src = (const uint4*)g_Wb;
        uint4* dst = (uint4*)Ws;
        #pragma unroll 2
        for (int i = tid; i < 256 * XSTR / 16; i += 512) dst[i] = src[i];
        for (int i = tid; i < gcnt * H; i += 512) {
            int gi = i / H, h = i - gi * H;
            idxH[gi * MAXH + h] = history[(size_t)bbase * H + i];
            idxR[gi * MAXH + h] = hregion[(size_t)bbase * H + i];
        }
        if (tid < 256) { b1s[tid] = b1[tid]; w2s[tid] = w2[tid]; }
        // zero rows [H,112)
        for (int i = tid; i < (112 - H) * (XSTR / 16); i += 512) {
            int r = H + i / (XSTR / 16), c = (i % (XSTR / 16)) * 16;
            *(uint4*)(Xs + r * XSTR + c) = make_uint4(0, 0, 0, 0);
        }
        if (wid == 0) {
            float v = E_dist[lane] + E_dist[lane + 32] + E_dist[lane + 64] + E_dist[lane + 96];
            #pragma unroll
            for (int o = 16; o; o >>= 1) v += __shfl_down_sync(0xffffffffu, v, o);
            if (lane == 0) miscF[0] = v;
        }
        if (tid < 128) build_tvec(bbase);
    }
    __syncthreads();
    // gather batch 0 (all 16 warps)
    for (int h = wid; h < H; h += 16) issue_row(h, idxH[h], idxR[h]);
    CPA_COMMIT(); CPA_WAIT0();
    __syncthreads();
    const float distsum = miscF[0];

    const int mw = wid >> 2;          // rows [32mw, 32mw+32) (mw==3: rows 96..111 only -> 1 m-tile)
    const int nw = wid & 3;           // cols [64nw, 64nw+64)
    const int g  = lane >> 2;
    const int tg = lane & 3;
    const int r0 = mw * 32 + g;
    const bool full_m = (mw < 3);

    for (int gi = 0; gi < gcnt; ++gi) {
        const int batch = bbase + gi;

        // ================= phase 1: GEMM + sx (X(gi), tvec(gi) valid) =================
        float acc[2][8][4];
        #pragma unroll
        for (int mt = 0; mt < 2; ++mt)
            #pragma unroll
            for (int nt = 0; nt < 8; ++nt)
                #pragma unroll
                for (int i = 0; i < 4; ++i) acc[mt][nt][i] = 0.f;
        {
            const unsigned char* Ar  = Xs + r0 * XSTR + tg * 8;
            const unsigned char* Br  = Ws + (nw * 64 + g) * XSTR + tg * 8;
            const unsigned char* Tvp = Tv + tg * 8;

            #pragma unroll 4
            for (int c = 0; c < 16; ++c) {
                const int co = c * 32;
                uint2 tt = *(const uint2*)(Tvp + co);
                uint32_t a0, a1, a2, a3, a4, a5, a6, a7;
                { uint2 t = *(const uint2*)(Ar + co);            a0 = bmul2(t.x, tt.x); a2 = bmul2(t.y, tt.y); }
                { uint2 t = *(const uint2*)(Ar + 8 * XSTR + co); a1 = bmul2(t.x, tt.x); a3 = bmul2(t.y, tt.y); }
                if (full_m) {
                    { uint2 t = *(const uint2*)(Ar + 16 * XSTR + co); a4 = bmul2(t.x, tt.x); a6 = bmul2(t.y, tt.y); }
                    { uint2 t = *(const uint2*)(Ar + 24 * XSTR + co); a5 = bmul2(t.x, tt.x); a7 = bmul2(t.y, tt.y); }
                    #pragma unroll
                    for (int nt = 0; nt < 8; ++nt) {
                        uint2 b = *(const uint2*)(Br + nt * 8 * XSTR + co);
                        mma_bf16(acc[0][nt], a0, a1, a2, a3, b.x, b.y);
                        mma_bf16(acc[1][nt], a4, a5, a6, a7, b.x, b.y);
                    }
                } else {
                    #pragma unroll
                    for (int nt = 0; nt < 8; ++nt) {
                        uint2 b = *(const uint2*)(Br + nt * 8 * XSTR + co);
                        mma_bf16(acc[0][nt], a0, a1, a2, a3, b.x, b.y);
                    }
                }
            }
            // sx: fp32 dot of raw row with tvec (16 warps, rows wid+16j)
            for (int h = wid; h < H; h += 16) {
                uint4 xv = ((const uint4*)(Xs + h * XSTR))[lane];
                uint4 tv = ((const uint4*)Tv)[lane];
                float s = dot8(xv, tv);
                #pragma unroll
                for (int o = 16; o; o >>= 1) s += __shfl_down_sync(0xffffffffu, s, o);
                if (lane == 0) sx[h] = s;
            }
        }
        __syncthreads();

        // ====== phase 2: gather X(gi+1) via cp.async (warps 4..15) | epilogue | tvec(gi+1) ======
        if (gi + 1 < gcnt && wid >= 4) {
            const int* ih = idxH + (gi + 1) * MAXH;
            const int* ir = idxR + (gi + 1) * MAXH;
            for (int h = wid - 4; h < H; h += 12) issue_row(h, ih[h], ir[h]);
        }
        CPA_COMMIT();
        {
            float s0 = 0.f, s1 = 0.f, s2 = 0.f, s3 = 0.f;
            #pragma unroll
            for (int nt = 0; nt < 8; ++nt) {
                int k0 = nw * 64 + nt * 8 + tg * 2;
                float w0 = w2s[k0], w1v = w2s[k0 + 1];
                float q0 = b1s[k0], q1 = b1s[k0 + 1];
                s0 += fmaxf(acc[0][nt][0] + q0, 0.f) * w0 + fmaxf(acc[0][nt][1] + q1, 0.f) * w1v;
                s1 += fmaxf(acc[0][nt][2] + q0, 0.f) * w0 + fmaxf(acc[0][nt][3] + q1, 0.f) * w1v;
                if (full_m) {
                    s2 += fmaxf(acc[1][nt][0] + q0, 0.f) * w0 + fmaxf(acc[1][nt][1] + q1, 0.f) * w1v;
                    s3 += fmaxf(acc[1][nt][2] + q0, 0.f) * w0 + fmaxf(acc[1][nt][3] + q1, 0.f) * w1v;
                }
            }
            s0 += __shfl_xor_sync(0xffffffffu, s0, 1); s0 += __shfl_xor_sync(0xffffffffu, s0, 2);
            s1 += __shfl_xor_sync(0xffffffffu, s1, 1); s1 += __shfl_xor_sync(0xffffffffu, s1, 2);
            if (full_m) {
                s2 += __shfl_xor_sync(0xffffffffu, s2, 1); s2 += __shfl_xor_sync(0xffffffffu, s2, 2);
                s3 += __shfl_xor_sync(0xffffffffu, s3, 1); s3 += __shfl_xor_sync(0xffffffffu, s3, 2);
            }
            if (tg == 0) {
                float* sp = spp + nw * 128;
                sp[r0]     = s0;
                sp[r0 + 8] = s1;
                if (full_m) { sp[r0 + 16] = s2; sp[r0 + 24] = s3; }
            }
        }
        if (tid < 128 && gi + 1 < gcnt) build_tvec(batch + 1);
        __syncthreads();

        // ================= phase 3: exp/out (warps 0-3) | cp.async drain (warps 4-15) =================
        if (tid < 128) {
            float eS = 0.f, eP = 0.f;
            if (tid < H) {
                float sc = spp[tid] + spp[128 + tid] + spp[256 + tid] + spp[384 + tid]
                         + tdist[batch] * distsum;
                float e = __expf(sc);
                if (idxH[gi * MAXH + tid] == target[batch]) e = 0.f;
                eS = e; eP = e * sx[tid];
            }
            #pragma unroll
            for (int o = 16; o; o >>= 1) {
                eS += __shfl_down_sync(0xffffffffu, eS, o);
                eP += __shfl_down_sync(0xffffffffu, eP, o);
            }
            if (lane == 0) { redS[wid] = eS; redS[8 + wid] = eP; }
        } else {
            CPA_WAIT0();
        }
        __syncthreads();
        if (tid == 0) {
            float S = redS[0] + redS[1] + redS[2] + redS[3];
            float P = redS[8] + redS[9] + redS[10] + redS[11];
            float pred = P / sqrtf(S);     // attn = exp_A / sum^BETA, BETA=0.5
            out[batch] = 1.f / (1.f + __expf(-pred));
        }
        // no extra barrier needed: phase1(gi+1) touches neither redS nor spp
    }
}

extern "C" void kernel_launch(void* const* d_in, const int* in_sizes, int n_in,
                              void* d_out, int out_size)
{
    const int*   history = (const int*)d_in[0];
    const int*   target  = (const int*)d_in[1];
    const int*   hregion = (const int*)d_in[2];
    const int*   tregion = (const int*)d_in[3];
    const float* tdist   = (const float*)d_in[4];
    const float* E_hist  = (const float*)d_in[5];
    const float* E_tgt   = (const float*)d_in[6];
    const float* E_reg   = (const float*)d_in[7];
    const float* E_dist  = (const float*)d_in[8];
    const float* W1      = (const float*)d_in[9];
    const float* b1      = (const float*)d_in[10];
    const float* w2      = (const float*)d_in[11];
    float* out = (float*)d_out;

    const int B = in_sizes[1];                 // target: [B]
    const int H = in_sizes[0] / B;             // history: [B,H]
    const int nEh = in_sizes[5];
    const int nEr = in_sizes[7];

    {
        long total = (long)nEh + nEr + 65536;
        int blocks = (int)((total + 255) / 256);
        convert_kernel<<<blocks, 256>>>(E_hist, E_reg, W1, nEh, nEr);
    }

    const int G = (B + 147) / 148;             // batches per persistent block (single wave)
    const int grid = (B + G - 1) / G;
    cudaFuncSetAttribute(nais_kernel, cudaFuncAttributeMaxDynamicSharedMemorySize, SMEM_BYTES);
    nais_kernel<<<grid, 512, SMEM_BYTES>>>(history, target, hregion, tregion, tdist,
                                           E_tgt, E_dist, b1, w2, out, B, H, G);
}

// round 11
// speedup vs baseline: 1.3249x; 1.3249x over previous
#include <cuda_runtime.h>
#include <cuda_bf16.h>
#include <cstdint>

// SW128 blocked-atom layout (atom = 8 rows x 64 bf16 = 1024B), XOR swizzle:
// byte(r,c) = (c>>6)*ACS + (r>>3)*1024 + (r&7)*128 + (((c&63)*2) ^ ((r&7)<<4))
static constexpr int ACS_X = 14336;   // (112/8)*1024
static constexpr int ACS_W = 32768;   // (256/8)*1024

__device__ __align__(16) __nv_bfloat16 g_Wsw[256 * 256];   // 128 KB, swizzled bf16 W1

__global__ void convert_w_kernel(const float* __restrict__ W1) {
    int e = blockIdx.x * blockDim.x + threadIdx.x;   // 65536
    int n = e >> 8, k = e & 255;
    uint32_t byte = (uint32_t)(k >> 6) * ACS_W + (uint32_t)(n >> 3) * 1024u
                  + (uint32_t)(n & 7) * 128u + ((((uint32_t)(k & 63)) * 2u) ^ ((uint32_t)(n & 7) << 4));
    g_Wsw[byte >> 1] = __float2bfloat16(W1[n * 256 + k]);
}

// smem: W 131072 | X 57344 | floats
static constexpr int SM_X  = 131072;
static constexpr int SM_FL = 188416;
static constexpr int SMEM_BYTES = SM_FL + 1184 * 4;   // 193152

__device__ __forceinline__ uint32_t smem_u32(const void* p) {
    return (uint32_t)__cvta_generic_to_shared(p);
}
__device__ __forceinline__ void ldsm4(uint32_t addr, uint32_t r[4]) {
    asm volatile("ldmatrix.sync.aligned.m8n8.x4.shared.b16 {%0,%1,%2,%3}, [%4];"
                 : "=r"(r[0]), "=r"(r[1]), "=r"(r[2]), "=r"(r[3]) : "r"(addr));
}
__device__ __forceinline__ void mma_bf16(float c[4], const uint32_t a[4], uint32_t b0, uint32_t b1) {
    asm volatile(
        "mma.sync.aligned.m16n8k16.row.col.f32.bf16.bf16.f32 "
        "{%0,%1,%2,%3}, {%4,%5,%6,%7}, {%8,%9}, {%0,%1,%2,%3};\n"
        : "+f"(c[0]), "+f"(c[1]), "+f"(c[2]), "+f"(c[3])
        : "r"(a[0]), "r"(a[1]), "r"(a[2]), "r"(a[3]), "r"(b0), "r"(b1));
}

__global__ __launch_bounds__(512, 1)
void nais_kernel(const int* __restrict__ history,
                 const int* __restrict__ target,
                 const int* __restrict__ hregion,
                 const int* __restrict__ tregion,
                 const float* __restrict__ tdist,
                 const float* __restrict__ E_hist,
                 const float* __restrict__ E_tgt,
                 const float* __restrict__ E_reg,
                 const float* __restrict__ E_dist,
                 const float* __restrict__ b1,
                 const float* __restrict__ w2,
                 float* __restrict__ out,
                 int B, int H, int G)
{
    extern __shared__ unsigned char smem[];
    unsigned char* Wsc = smem;                 // swizzled W [256 x 256 bf16]
    unsigned char* Xsc = smem + SM_X;          // swizzled X [112 x 256 bf16]
    float* fl    = (float*)(smem + SM_FL);
    float* b1s   = fl;            // 256
    float* w2s   = fl + 256;      // 256
    float* sx    = fl + 512;      // 128
    float* spp   = fl + 640;      // 4 x 128
    float* redS  = fl + 1152;     // 16
    float* miscF = fl + 1168;     // 1

    const int tid  = threadIdx.x;
    const int wid  = tid >> 5;
    const int lane = tid & 31;

    const int bbase = blockIdx.x * G;
    if (bbase >= B) return;
    const int gcnt = min(G, B - bbase);

    // ---------------- one-time staging ----------------
    {
        const uint4* src = (const uint4*)g_Wsw;
        uint4* dst = (uint4*)Wsc;
        #pragma unroll 4
        for (int i = tid; i < 131072 / 16; i += 512) dst[i] = src[i];
        if (tid < 256) { b1s[tid] = b1[tid]; w2s[tid] = w2[tid]; }
        if (wid == 0) {
            float v = E_dist[lane] + E_dist[lane + 32] + E_dist[lane + 64] + E_dist[lane + 96];
            #pragma unroll
            for (int o = 16; o; o >>= 1) v += __shfl_down_sync(0xffffffffu, v, o);
            if (lane == 0) miscF[0] = v;
        }
    }
    __syncthreads();
    const float distsum = miscF[0];

    // warp tiling
    const int mw = wid >> 2;              // mw<3: rows [32mw,32mw+32); mw==3: rows 96-111
    const int nw = wid & 3;               // cols [64nw, 64nw+64)
    const int g  = lane >> 2;
    const int tg = lane & 3;
    const int r0 = mw * 32 + g;
    const bool full_m = (mw < 3);

    // ldmatrix lane constants
    const int e8  = (lane >> 3) & 1;
    const int e16 = lane >> 4;
    const int l7  = lane & 7;
    const uint32_t smW = smem_u32(Wsc);
    const uint32_t smX = smem_u32(Xsc);
    // A: row = R0 + e8*8 + l7, k-half sel = e16
    const uint32_t baseA = smX + (uint32_t)(mw * 4 + e8) * 1024u + (uint32_t)l7 * 128u;
    const uint32_t QA = ((uint32_t)e16 * 16u) ^ ((uint32_t)l7 << 4);
    // B: n = nw*64 + nt4*16 + e16*8 + l7, k-half sel = e8
    const uint32_t baseB = smW + (uint32_t)(nw * 8 + e16) * 1024u + (uint32_t)l7 * 128u;
    const uint32_t QB = ((uint32_t)e8 * 16u) ^ ((uint32_t)l7 << 4);

    for (int gi = 0; gi < gcnt; ++gi) {
        const int batch = bbase + gi;
        const int tgtI  = target[batch];

        // ---------------- gather X = hist (*) tgt into swizzled SMEM + fp32 row sums ----------------
        {
            const int tregI = tregion[batch];
            float4 t1 = *(const float4*)(E_tgt + (size_t)tgtI  * 128 + 4 * lane);
            float4 t2 = *(const float4*)(E_reg + (size_t)tregI * 128 + 4 * lane);
            const uint32_t inb = (((uint32_t)(lane & 15)) * 8u);     // ^ row-xor added per row
            const uint32_t acH = (uint32_t)(lane >> 4) * (uint32_t)ACS_X;          // hist atom col 0/1
            const uint32_t acR = (uint32_t)(2 + (lane >> 4)) * (uint32_t)ACS_X;    // region atom col 2/3
            for (int h = wid; h < H; h += 16) {
                int item = history[(size_t)batch * H + h];
                int rg   = hregion[(size_t)batch * H + h];
                float4 v1 = *(const float4*)(E_hist + (size_t)item * 128 + 4 * lane);
                float4 v2 = *(const float4*)(E_reg  + (size_t)rg   * 128 + 4 * lane);
                float x0 = v1.x * t1.x, x1 = v1.y * t1.y, x2 = v1.z * t1.z, x3 = v1.w * t1.w;
                float y0 = v2.x * t2.x, y1 = v2.y * t2.y, y2 = v2.z * t2.z, y3 = v2.w * t2.w;
                float s = (x0 + x1) + (x2 + x3) + (y0 + y1) + (y2 + y3);
                union { __nv_bfloat16 q[4]; uint2 u; } p1, p2;
                p1.q[0] = __float2bfloat16(x0); p1.q[1] = __float2bfloat16(x1);
                p1.q[2] = __float2bfloat16(x2); p1.q[3] = __float2bfloat16(x3);
                p2.q[0] = __float2bfloat16(y0); p2.q[1] = __float2bfloat16(y1);
                p2.q[2] = __float2bfloat16(y2); p2.q[3] = __float2bfloat16(y3);
                uint32_t bh = (uint32_t)(h >> 3) * 1024u + (uint32_t)(h & 7) * 128u;
                uint32_t ib = inb ^ ((uint32_t)(h & 7) << 4);
                *(uint2*)(Xsc + acH + bh + ib) = p1.u;
                *(uint2*)(Xsc + acR + bh + ib) = p2.u;
                #pragma unroll
                for (int o = 16; o; o >>= 1) s += __shfl_down_sync(0xffffffffu, s, o);
                if (lane == 0) sx[h] = s;
            }
        }
        __syncthreads();

        // ---------------- GEMM via ldmatrix (conflict-free SW128) ----------------
        {
            float acc[2][8][4];
            #pragma unroll
            for (int mt = 0; mt < 2; ++mt)
                #pragma unroll
                for (int nt = 0; nt < 8; ++nt)
                    #pragma unroll
                    for (int i = 0; i < 4; ++i) acc[mt][nt][i] = 0.f;

            #pragma unroll
            for (int kk = 0; kk < 16; ++kk) {
                const uint32_t kA = (uint32_t)(kk >> 2) * (uint32_t)ACS_X + ((((uint32_t)(kk & 3)) << 5) ^ QA);
                const uint32_t kB = (uint32_t)(kk >> 2) * (uint32_t)ACS_W + ((((uint32_t)(kk & 3)) << 5) ^ QB);
                uint32_t a0[4], a1[4];
                ldsm4(baseA + kA, a0);
                if (full_m) ldsm4(baseA + 2048u + kA, a1);
                #pragma unroll
                for (int nt4 = 0; nt4 < 4; ++nt4) {
                    uint32_t b[4];
                    ldsm4(baseB + (uint32_t)nt4 * 2048u + kB, b);
                    mma_bf16(acc[0][2 * nt4],     a0, b[0], b[1]);
                    mma_bf16(acc[0][2 * nt4 + 1], a0, b[2], b[3]);
                    if (full_m) {
                        mma_bf16(acc[1][2 * nt4],     a1, b[0], b[1]);
                        mma_bf16(acc[1][2 * nt4 + 1], a1, b[2], b[3]);
                    }
                }
            }

            // epilogue: +b1, relu, dot w2 over this warp's n64 chunk
            float s0 = 0.f, s1 = 0.f, s2 = 0.f, s3 = 0.f;
            #pragma unroll
            for (int nt = 0; nt < 8; ++nt) {
                int k0 = nw * 64 + nt * 8 + tg * 2;
                float w0 = w2s[k0], w1v = w2s[k0 + 1];
                float q0 = b1s[k0], q1 = b1s[k0 + 1];
                s0 += fmaxf(acc[0][nt][0] + q0, 0.f) * w0 + fmaxf(acc[0][nt][1] + q1, 0.f) * w1v;
                s1 += fmaxf(acc[0][nt][2] + q0, 0.f) * w0 + fmaxf(acc[0][nt][3] + q1, 0.f) * w1v;
                if (full_m) {
                    s2 += fmaxf(acc[1][nt][0] + q0, 0.f) * w0 + fmaxf(acc[1][nt][1] + q1, 0.f) * w1v;
                    s3 += fmaxf(acc[1][nt][2] + q0, 0.f) * w0 + fmaxf(acc[1][nt][3] + q1, 0.f) * w1v;
                }
            }
            s0 += __shfl_xor_sync(0xffffffffu, s0, 1); s0 += __shfl_xor_sync(0xffffffffu, s0, 2);
            s1 += __shfl_xor_sync(0xffffffffu, s1, 1); s1 += __shfl_xor_sync(0xffffffffu, s1, 2);
            if (full_m) {
                s2 += __shfl_xor_sync(0xffffffffu, s2, 1); s2 += __shfl_xor_sync(0xffffffffu, s2, 2);
                s3 += __shfl_xor_sync(0xffffffffu, s3, 1); s3 += __shfl_xor_sync(0xffffffffu, s3, 2);
            }
            if (tg == 0) {
                float* sp = spp + nw * 128;
                sp[r0]     = s0;      // rows mw*32 + g
                sp[r0 + 8] = s1;      // rows +8
                if (full_m) { sp[r0 + 16] = s2; sp[r0 + 24] = s3; }
            }
        }
        __syncthreads();

        // ---------------- masked exp, BETA=0.5 normalize, pred, sigmoid ----------------
        {
            float eS = 0.f, eP = 0.f;
            if (tid < 128 && tid < H) {
                float sc = spp[tid] + spp[128 + tid] + spp[256 + tid] + spp[384 + tid]
                         + tdist[batch] * distsum;
                float e = expf(sc);
                if (history[(size_t)batch * H + tid] == tgtI) e = 0.f;
                eS = e; eP = e * sx[tid];
            }
            #pragma unroll
            for (int o = 16; o; o >>= 1) {
                eS += __shfl_down_sync(0xffffffffu, eS, o);
                eP += __shfl_down_sync(0xffffffffu, eP, o);
            }
            if (wid < 4 && lane == 0) { redS[wid] = eS; redS[8 + wid] = eP; }
        }
        __syncthreads();
        if (tid == 0) {
            float S = redS[0] + redS[1] + redS[2] + redS[3];
            float P = redS[8] + redS[9] + redS[10] + redS[11];
            float pred = P / sqrtf(S);     // attn = exp_A / sum^BETA, BETA=0.5
            out[batch] = 1.f / (1.f + expf(-pred));
        }
        __syncthreads();   // protect sx / Xs / spp before next batch overwrites
    }
}

extern "C" void kernel_launch(void* const* d_in, const int* in_sizes, int n_in,
                              void* d_out, int out_size)
{
    const int*   history = (const int*)d_in[0];
    const int*   target  = (const int*)d_in[1];
    const int*   hregion = (const int*)d_in[2];
    const int*   tregion = (const int*)d_in[3];
    const float* tdist   = (const float*)d_in[4];
    const float* E_hist  = (const float*)d_in[5];
    const float* E_tgt   = (const float*)d_in[6];
    const float* E_reg   = (const float*)d_in[7];
    const float* E_dist  = (const float*)d_in[8];
    const float* W1      = (const float*)d_in[9];
    const float* b1      = (const float*)d_in[10];
    const float* w2      = (const float*)d_in[11];
    float* out = (float*)d_out;

    const int B = in_sizes[1];                 // target: [B]
    const int H = in_sizes[0] / B;             // history: [B,H]

    convert_w_kernel<<<64, 1024>>>(W1);        // W1 only: ~3us

    const int G = (B + 147) / 148;             // batches per persistent block (single wave)
    const int grid = (B + G - 1) / G;
    cudaFuncSetAttribute(nais_kernel, cudaFuncAttributeMaxDynamicSharedMemorySize, SMEM_BYTES);
    nais_kernel<<<grid, 512, SMEM_BYTES>>>(history, target, hregion, tregion, tdist,
                                           E_hist, E_tgt, E_reg, E_dist,
                                           b1, w2, out, B, H, G);
}